// round 15
// baseline (speedup 1.0000x reference)
#include <cuda_runtime.h>
#include <cuda_fp16.h>
#include <cstdint>

#define NN 100000
#define NE 1600000
#define NSPLIT 50176                         // = 392*128 = 196*256

// ---- static device scratch (no allocation allowed) ----
__device__ __align__(16) float  g_dinv[NN];
__device__ __align__(16) int    g_col[NE];
__device__ __align__(16) int    g_rowptr[NN];   // segment start (atomic layout)
__device__ __align__(16) int    g_deg[NN];
__device__ __align__(16) int    g_cursor[NN];
__device__ int g_total;
// ping-pong hs buffers (odd layers -> A, even layers -> B)
__device__ __align__(16) __half g_hsA[12800000];   // layers 1(128),3(32),5(8)
__device__ __align__(16) __half g_hsB[6400000];    // layers 2(64),4(16)
// fp16 activations
__device__ __align__(16) __half g_ahA[12800000];   // L1 act (128)
__device__ __align__(16) __half g_ahB[6400000];    // L2 act (64)
__device__ __align__(16) float  g_act[3200000];    // L3 (32) / L4 (16) act fp32
// W splits (transposed [n][k])
__device__ __align__(16) __half g_w1h[16384], g_w1l[16384];
__device__ __align__(16) __half g_w2h[8192],  g_w2l[8192];
__device__ __align__(16) __half g_w3h[2048],  g_w3l[2048];
__device__ int g_is64;

// ---------------- small helpers ----------------
__device__ __forceinline__ uint32_t smem_u32(const void* p) {
    uint32_t a;
    asm("{ .reg .u64 t; cvta.to.shared.u64 t, %1; cvt.u32.u64 %0, t; }"
        : "=r"(a) : "l"(p));
    return a;
}
__device__ __forceinline__ void ldsm4(uint32_t* r, uint32_t addr) {
    asm volatile("ldmatrix.sync.aligned.m8n8.x4.shared.b16 {%0,%1,%2,%3}, [%4];"
        : "=r"(r[0]), "=r"(r[1]), "=r"(r[2]), "=r"(r[3]) : "r"(addr));
}
__device__ __forceinline__ void ldsm2(uint32_t* r, uint32_t addr) {
    asm volatile("ldmatrix.sync.aligned.m8n8.x2.shared.b16 {%0,%1}, [%2];"
        : "=r"(r[0]), "=r"(r[1]) : "r"(addr));
}
__device__ __forceinline__ void mma16816(float* c, const uint32_t* a,
                                         const uint32_t* b) {
    asm volatile("mma.sync.aligned.m16n8k16.row.col.f32.f16.f16.f32 "
        "{%0,%1,%2,%3}, {%4,%5,%6,%7}, {%8,%9}, {%0,%1,%2,%3};"
        : "+f"(c[0]), "+f"(c[1]), "+f"(c[2]), "+f"(c[3])
        : "r"(a[0]), "r"(a[1]), "r"(a[2]), "r"(a[3]), "r"(b[0]), "r"(b[1]));
}

// ---------------- sniff + zero deg (merged) ----------------
__global__ void k_sniff_zero(const unsigned int* __restrict__ w) {
    int i = blockIdx.x * blockDim.x + threadIdx.x;
    if (i < NN) g_deg[i] = 0;
    if (i == 0) {
        g_total = 0;
        int is64 = 1;
        for (int q = 0; q < 128; q++)
            if (w[2 * q + 1] != 0u) { is64 = 0; break; }
        g_is64 = is64;
    }
}

__global__ void k_deg(const void* __restrict__ ei) {
    int e = blockIdx.x * blockDim.x + threadIdx.x;
    if (e >= NE) return;
    long long s, d;
    if (g_is64) {
        const long long* p = (const long long*)ei;
        s = p[e]; d = p[NE + e];
    } else {
        const int* p = (const int*)ei;
        s = p[e]; d = p[NE + e];
    }
    if (s >= 0 && s < NN && d >= 0 && d < NN)
        atomicAdd(&g_deg[(int)d], 1);
}

// scan-free CSR: each node grabs a segment via one global atomic
__global__ void k_finalize_csr() {
    int i = blockIdx.x * blockDim.x + threadIdx.x;
    if (i >= NN) return;
    int deg = g_deg[i];
    g_rowptr[i] = atomicAdd(&g_total, deg);
    g_cursor[i] = 0;
    g_dinv[i] = rsqrtf((float)deg + 1.0f);
}

__global__ void k_fill(const void* __restrict__ ei, int e0, int e1) {
    int e = e0 + blockIdx.x * blockDim.x + threadIdx.x;
    if (e >= e1) return;
    long long s, d;
    if (g_is64) {
        const long long* p = (const long long*)ei;
        s = p[e]; d = p[NE + e];
    } else {
        const int* p = (const int*)ei;
        s = p[e]; d = p[NE + e];
    }
    if (s >= 0 && s < NN && d >= 0 && d < NN) {
        int pos = g_rowptr[(int)d] + atomicAdd(&g_cursor[(int)d], 1);
        g_col[pos] = (int)s;
    }
}

// ---------------- W transpose + fp16 split ----------------
__global__ void k_wsplit1(const float* __restrict__ W) {
    int idx = blockIdx.x * blockDim.x + threadIdx.x;
    if (idx >= 128 * 128) return;
    int n = idx >> 7, k = idx & 127;
    float v = W[k * 128 + n];
    __half h = __float2half_rn(v);
    g_w1h[idx] = h;
    g_w1l[idx] = __float2half_rn(v - __half2float(h));
}
__global__ void k_wsplit2(const float* __restrict__ W) {
    int idx = blockIdx.x * blockDim.x + threadIdx.x;
    if (idx >= 64 * 128) return;
    int n = idx >> 7, k = idx & 127;
    float v = W[k * 64 + n];
    __half h = __float2half_rn(v);
    g_w2h[idx] = h;
    g_w2l[idx] = __float2half_rn(v - __half2float(h));
}
__global__ void k_wsplit3(const float* __restrict__ W) {
    int idx = blockIdx.x * blockDim.x + threadIdx.x;
    if (idx >= 32 * 64) return;
    int n = idx >> 6, k = idx & 63;
    float v = W[k * 32 + n];
    __half h = __float2half_rn(v);
    g_w3h[idx] = h;
    g_w3l[idx] = __float2half_rn(v - __half2float(h));
}

// =============== layer-1 GEMM: A fp16, W split, fp32 acc ===================
// CTA: 128 rows x 128 cols, K=128, 8 warps (4m x 2n). Writes RAW h -> g_hsA.
#define STR 136
__global__ __launch_bounds__(256) void gemm_mma1(const float* __restrict__ in) {
    extern __shared__ __align__(16) __half sm[];
    __half* ah = sm;
    __half* bh = ah + 128 * STR;
    __half* bl = bh + 128 * STR;
    int tid = threadIdx.x;
    int rowBase = blockIdx.x * 128;

#pragma unroll
    for (int i = 0; i < 16; i++) {
        int idx = tid + i * 256;
        int r = idx >> 5;
        int c4 = (idx & 31) * 4;
        int gr = rowBase + r;
        float4 v = (gr < NN) ? *(const float4*)&in[(size_t)gr * 128 + c4]
                             : make_float4(0.f, 0.f, 0.f, 0.f);
        __half2 hp0 = __floats2half2_rn(v.x, v.y);
        __half2 hp1 = __floats2half2_rn(v.z, v.w);
        int off = r * STR + c4;
        *(__half2*)&ah[off] = hp0;
        *(__half2*)&ah[off + 2] = hp1;
    }
#pragma unroll
    for (int i = 0; i < 8; i++) {
        int idx = tid + i * 256;
        int r = idx >> 4, g = idx & 15;
        int off = r * STR + g * 8;
        *(uint4*)&bh[off] = *(const uint4*)&g_w1h[r * 128 + g * 8];
        *(uint4*)&bl[off] = *(const uint4*)&g_w1l[r * 128 + g * 8];
    }
    __syncthreads();

    int wid = tid >> 5, lane = tid & 31;
    int wm = wid & 3, wn = wid >> 2;
    uint32_t ahb = smem_u32(ah);
    uint32_t bhb = smem_u32(bh), blb = smem_u32(bl);
    int arow = wm * 32 + (lane & 15);
    int acol = (lane >> 4) * 8;
    int brow = wn * 64 + (lane & 7);
    int bcol = ((lane >> 3) & 1) * 8;

    float acc[2][8][4];
#pragma unroll
    for (int m = 0; m < 2; m++)
#pragma unroll
        for (int n = 0; n < 8; n++)
#pragma unroll
            for (int q = 0; q < 4; q++) acc[m][n][q] = 0.0f;

#pragma unroll
    for (int kk = 0; kk < 8; kk++) {
        uint32_t afh[2][4];
#pragma unroll
        for (int m = 0; m < 2; m++) {
            uint32_t ao = (uint32_t)(((arow + m * 16) * STR + kk * 16 + acol) * 2);
            ldsm4(afh[m], ahb + ao);
        }
        uint32_t bfh[8][2], bfl[8][2];
#pragma unroll
        for (int n = 0; n < 8; n++) {
            uint32_t bo = (uint32_t)(((brow + n * 8) * STR + kk * 16 + bcol) * 2);
            ldsm2(bfh[n], bhb + bo);
            ldsm2(bfl[n], blb + bo);
        }
#pragma unroll
        for (int m = 0; m < 2; m++)
#pragma unroll
            for (int n = 0; n < 8; n++) {
                mma16816(acc[m][n], afh[m], bfh[n]);
                mma16816(acc[m][n], afh[m], bfl[n]);
            }
    }

    int r0 = rowBase + wm * 32 + (lane >> 2);
    int cbase = wn * 64 + 2 * (lane & 3);
#pragma unroll
    for (int m = 0; m < 2; m++) {
        int ra = r0 + m * 16, rb = ra + 8;
#pragma unroll
        for (int n = 0; n < 8; n++) {
            int col = cbase + n * 8;
            if (ra < NN) {
                __half2 p = __floats2half2_rn(acc[m][n][0], acc[m][n][1]);
                *(uint32_t*)&g_hsA[(size_t)ra * 128 + col] = *(uint32_t*)&p;
            }
            if (rb < NN) {
                __half2 p = __floats2half2_rn(acc[m][n][2], acc[m][n][3]);
                *(uint32_t*)&g_hsA[(size_t)rb * 128 + col] = *(uint32_t*)&p;
            }
        }
    }
}

// =============== generic mma GEMM: [128 rows, FIN] x [FIN, FOUT] ===========
// A single fp16, W split. Writes hs = dinv*h.
template <int FIN, int FOUT>
__global__ __launch_bounds__(256) void gemm_mmaT(const __half* __restrict__ Ah,
                                                 __half* __restrict__ hsd,
                                                 int rowBase0) {
    constexpr int AST = FIN + 8;
    constexpr int GPR = FIN / 8;
    constexpr int NT = FOUT / 16;
    extern __shared__ __align__(16) __half sm[];
    __half* ah = sm;
    __half* bh = ah + 128 * AST;
    __half* bl = bh + FOUT * AST;
    int tid = threadIdx.x;
    int rowBase = rowBase0 + blockIdx.x * 128;

    const __half* Bh = (FIN == 128) ? g_w2h : g_w3h;
    const __half* Bl = (FIN == 128) ? g_w2l : g_w3l;

#pragma unroll
    for (int i = 0; i < FIN / 16; i++) {
        int idx = tid + i * 256;
        int r = idx / GPR, g = idx % GPR;
        int gr = rowBase + r;
        int off = r * AST + g * 8;
        if (gr < NN) {
            *(uint4*)&ah[off] = *(const uint4*)&Ah[(size_t)gr * FIN + g * 8];
        } else {
            *(uint4*)&ah[off] = make_uint4(0, 0, 0, 0);
        }
    }
#pragma unroll
    for (int i = 0; i < (FOUT * GPR + 255) / 256; i++) {
        int idx = tid + i * 256;
        if (idx < FOUT * GPR) {
            int r = idx / GPR, g = idx % GPR;
            int off = r * AST + g * 8;
            *(uint4*)&bh[off] = *(const uint4*)&Bh[r * FIN + g * 8];
            *(uint4*)&bl[off] = *(const uint4*)&Bl[r * FIN + g * 8];
        }
    }
    __syncthreads();

    int wid = tid >> 5, lane = tid & 31;
    int wm = wid & 3, wn = wid >> 2;
    uint32_t ahb = smem_u32(ah);
    uint32_t bhb = smem_u32(bh), blb = smem_u32(bl);
    int arow = wm * 32 + (lane & 15);
    int acol = (lane >> 4) * 8;
    int brow = wn * (FOUT / 2) + (lane & 7);
    int bcol = ((lane >> 3) & 1) * 8;

    float acc[2][NT][4];
#pragma unroll
    for (int m = 0; m < 2; m++)
#pragma unroll
        for (int n = 0; n < NT; n++)
#pragma unroll
            for (int q = 0; q < 4; q++) acc[m][n][q] = 0.0f;

#pragma unroll
    for (int kk = 0; kk < FIN / 16; kk++) {
        uint32_t afh[2][4];
#pragma unroll
        for (int m = 0; m < 2; m++) {
            uint32_t ao = (uint32_t)(((arow + m * 16) * AST + kk * 16 + acol) * 2);
            ldsm4(afh[m], ahb + ao);
        }
        uint32_t bfh[NT][2], bfl[NT][2];
#pragma unroll
        for (int n = 0; n < NT; n++) {
            uint32_t bo = (uint32_t)(((brow + n * 8) * AST + kk * 16 + bcol) * 2);
            ldsm2(bfh[n], bhb + bo);
            ldsm2(bfl[n], blb + bo);
        }
#pragma unroll
        for (int m = 0; m < 2; m++)
#pragma unroll
            for (int n = 0; n < NT; n++) {
                mma16816(acc[m][n], afh[m], bfh[n]);
                mma16816(acc[m][n], afh[m], bfl[n]);
            }
    }

    int r0 = rowBase + wm * 32 + (lane >> 2);
    int cbase = wn * (FOUT / 2) + 2 * (lane & 3);
#pragma unroll
    for (int m = 0; m < 2; m++) {
        int ra = r0 + m * 16, rb = ra + 8;
        float da = (ra < NN) ? g_dinv[ra] : 0.0f;
        float db = (rb < NN) ? g_dinv[rb] : 0.0f;
#pragma unroll
        for (int n = 0; n < NT; n++) {
            int col = cbase + n * 8;
            if (ra < NN) {
                __half2 p = __floats2half2_rn(acc[m][n][0] * da, acc[m][n][1] * da);
                *(uint32_t*)&hsd[(size_t)ra * FOUT + col] = *(uint32_t*)&p;
            }
            if (rb < NN) {
                __half2 p = __floats2half2_rn(acc[m][n][2] * db, acc[m][n][3] * db);
                *(uint32_t*)&hsd[(size_t)rb * FOUT + col] = *(uint32_t*)&p;
            }
        }
    }
}

// ---------------- GEMM, layers 4-5 (FFMA) ----------------
template <int FIN, int FOUT>
__global__ __launch_bounds__(256) void gemm_small(const float* __restrict__ in,
                                                  const float* __restrict__ W,
                                                  __half* __restrict__ hsd,
                                                  int rowBase0) {
    __shared__ float ws[FIN * FOUT];
    __shared__ float xs[256][9];
    int tid = threadIdx.x;
    for (int i = tid; i < FIN * FOUT; i += 256) ws[i] = W[i];

    int rowBase = rowBase0 + blockIdx.x * 256;
    int row = rowBase + tid;
    float acc[FOUT];
#pragma unroll
    for (int j = 0; j < FOUT; j++) acc[j] = 0.0f;

    for (int k0 = 0; k0 < FIN; k0 += 8) {
#pragma unroll
        for (int i = 0; i < 8; i++) {
            int idx = tid + i * 256;
            int r = idx >> 3, c = idx & 7;
            int gr = rowBase + r;
            xs[r][c] = (gr < NN) ? in[(size_t)gr * FIN + k0 + c] : 0.0f;
        }
        __syncthreads();
#pragma unroll
        for (int k = 0; k < 8; k++) {
            float xv = xs[tid][k];
            const float* wrow = &ws[(k0 + k) * FOUT];
#pragma unroll
            for (int j = 0; j < FOUT; j++)
                acc[j] = fmaf(xv, wrow[j], acc[j]);
        }
        __syncthreads();
    }

    if (row < NN) {
        float dv = g_dinv[row];
#pragma unroll
        for (int j = 0; j < FOUT; j += 8) {
            __half2 ph[4];
#pragma unroll
            for (int q = 0; q < 4; q++)
                ph[q] = __floats2half2_rn(acc[j + 2 * q] * dv,
                                          acc[j + 2 * q + 1] * dv);
            *(uint4*)&hsd[(size_t)row * FOUT + j] = *(uint4*)ph;
        }
    }
}

// ---- aggregate layer 1: raw fp16 h (g_hsA), per-edge dinv; fp16 act ----
__global__ __launch_bounds__(256) void aggregate1(const float* __restrict__ bias,
                                                  int base) {
    constexpr int F = 128;
    int warp = (blockIdx.x * 256 + threadIdx.x) >> 5;
    int lane = threadIdx.x & 31;
    int node = base + warp * 2 + (lane >> 4);
    int c8 = (lane & 15) * 8;
    if (node >= NN) return;

    float dvn = g_dinv[node];
    int beg = g_rowptr[node];
    int end = beg + g_deg[node];

    float a[8];
    {
        uint4 raw = *(const uint4*)&g_hsA[(size_t)node * F + c8];
        const __half2* hp = (const __half2*)&raw;
#pragma unroll
        for (int q = 0; q < 4; q++) {
            float2 f = __half22float2(hp[q]);
            a[2 * q]     = dvn * f.x;
            a[2 * q + 1] = dvn * f.y;
        }
    }

    int e = beg;
    for (; e + 1 < end; e += 2) {
        int s0 = g_col[e];
        int s1 = g_col[e + 1];
        float d0 = g_dinv[s0];
        float d1 = g_dinv[s1];
        uint4 r0 = *(const uint4*)&g_hsA[(size_t)s0 * F + c8];
        uint4 r1 = *(const uint4*)&g_hsA[(size_t)s1 * F + c8];
        const __half2* h0 = (const __half2*)&r0;
        const __half2* h1 = (const __half2*)&r1;
#pragma unroll
        for (int q = 0; q < 4; q++) {
            float2 f0 = __half22float2(h0[q]);
            float2 f1 = __half22float2(h1[q]);
            a[2 * q]     = fmaf(d0, f0.x, fmaf(d1, f1.x, a[2 * q]));
            a[2 * q + 1] = fmaf(d0, f0.y, fmaf(d1, f1.y, a[2 * q + 1]));
        }
    }
    if (e < end) {
        int s = g_col[e];
        float ds = g_dinv[s];
        uint4 r = *(const uint4*)&g_hsA[(size_t)s * F + c8];
        const __half2* h = (const __half2*)&r;
#pragma unroll
        for (int q = 0; q < 4; q++) {
            float2 f = __half22float2(h[q]);
            a[2 * q]     = fmaf(ds, f.x, a[2 * q]);
            a[2 * q + 1] = fmaf(ds, f.y, a[2 * q + 1]);
        }
    }

    __half hh[8];
#pragma unroll
    for (int q = 0; q < 8; q++) {
        float b = bias[c8 + q];
        hh[q] = __float2half_rn(fmaxf(fmaf(dvn, a[q], b), 0.0f));
    }
    *(uint4*)&g_ahA[(size_t)node * F + c8] = *(uint4*)hh;
}

// ---- aggregate layer 2 (F=64, hs in g_hsB pre-scaled): fp16 act out ----
__global__ __launch_bounds__(256) void agg_split64(const float* __restrict__ bias,
                                                   int base) {
    constexpr int F = 64;
    int warp = (blockIdx.x * 256 + threadIdx.x) >> 5;
    int lane = threadIdx.x & 31;
    int node = base + warp * 4 + lane / 8;
    int c8 = (lane % 8) * 8;
    if (node >= NN) return;

    float dvn = g_dinv[node];
    int beg = g_rowptr[node];
    int end = beg + g_deg[node];

    float a[8];
    {
        uint4 raw = *(const uint4*)&g_hsB[(size_t)node * F + c8];
        const __half2* hp = (const __half2*)&raw;
#pragma unroll
        for (int q = 0; q < 4; q++) {
            float2 f = __half22float2(hp[q]);
            a[2 * q] = f.x;
            a[2 * q + 1] = f.y;
        }
    }
    int e = beg;
    for (; e + 1 < end; e += 2) {
        int s0 = g_col[e];
        int s1 = g_col[e + 1];
        uint4 r0 = *(const uint4*)&g_hsB[(size_t)s0 * F + c8];
        uint4 r1 = *(const uint4*)&g_hsB[(size_t)s1 * F + c8];
        const __half2* h0 = (const __half2*)&r0;
        const __half2* h1 = (const __half2*)&r1;
#pragma unroll
        for (int q = 0; q < 4; q++) {
            float2 f0 = __half22float2(h0[q]);
            float2 f1 = __half22float2(h1[q]);
            a[2 * q]     += f0.x + f1.x;
            a[2 * q + 1] += f0.y + f1.y;
        }
    }
    if (e < end) {
        int s = g_col[e];
        uint4 r = *(const uint4*)&g_hsB[(size_t)s * F + c8];
        const __half2* h = (const __half2*)&r;
#pragma unroll
        for (int q = 0; q < 4; q++) {
            float2 f = __half22float2(h[q]);
            a[2 * q]     += f.x;
            a[2 * q + 1] += f.y;
        }
    }

    __half hh[8];
#pragma unroll
    for (int q = 0; q < 8; q++) {
        float b = bias[c8 + q];
        hh[q] = __float2half_rn(fmaxf(fmaf(dvn, a[q], b), 0.0f));
    }
    *(uint4*)&g_ahB[(size_t)node * F + c8] = *(uint4*)hh;
}

// ---- aggregate layers 3-5: hs pre-scaled; fp32 out ----
template <int F>
__global__ __launch_bounds__(256) void aggregate2(const float* __restrict__ bias,
                                                  float* __restrict__ outp,
                                                  const __half* __restrict__ hs,
                                                  int base) {
    constexpr int L = F / 8;
    constexpr int NPW = 32 / L;
    int warp = (blockIdx.x * 256 + threadIdx.x) >> 5;
    int lane = threadIdx.x & 31;
    int node = base + warp * NPW + lane / L;
    int c8 = (lane % L) * 8;
    if (node >= NN) return;

    float dvn = g_dinv[node];
    int beg = g_rowptr[node];
    int end = beg + g_deg[node];

    float a[8];
    {
        uint4 raw = *(const uint4*)&hs[(size_t)node * F + c8];
        const __half2* hp = (const __half2*)&raw;
#pragma unroll
        for (int q = 0; q < 4; q++) {
            float2 f = __half22float2(hp[q]);
            a[2 * q] = f.x;
            a[2 * q + 1] = f.y;
        }
    }
    int e = beg;
    for (; e + 1 < end; e += 2) {
        int s0 = g_col[e];
        int s1 = g_col[e + 1];
        uint4 r0 = *(const uint4*)&hs[(size_t)s0 * F + c8];
        uint4 r1 = *(const uint4*)&hs[(size_t)s1 * F + c8];
        const __half2* h0 = (const __half2*)&r0;
        const __half2* h1 = (const __half2*)&r1;
#pragma unroll
        for (int q = 0; q < 4; q++) {
            float2 f0 = __half22float2(h0[q]);
            float2 f1 = __half22float2(h1[q]);
            a[2 * q]     += f0.x + f1.x;
            a[2 * q + 1] += f0.y + f1.y;
        }
    }
    if (e < end) {
        int s = g_col[e];
        uint4 r = *(const uint4*)&hs[(size_t)s * F + c8];
        const __half2* h = (const __half2*)&r;
#pragma unroll
        for (int q = 0; q < 4; q++) {
            float2 f = __half22float2(h[q]);
            a[2 * q]     += f.x;
            a[2 * q + 1] += f.y;
        }
    }

    float4 b0 = *(const float4*)&bias[c8];
    float4 b1 = *(const float4*)&bias[c8 + 4];
    float4 o0, o1;
    o0.x = fmaxf(fmaf(dvn, a[0], b0.x), 0.0f);
    o0.y = fmaxf(fmaf(dvn, a[1], b0.y), 0.0f);
    o0.z = fmaxf(fmaf(dvn, a[2], b0.z), 0.0f);
    o0.w = fmaxf(fmaf(dvn, a[3], b0.w), 0.0f);
    o1.x = fmaxf(fmaf(dvn, a[4], b1.x), 0.0f);
    o1.y = fmaxf(fmaf(dvn, a[5], b1.y), 0.0f);
    o1.z = fmaxf(fmaf(dvn, a[6], b1.z), 0.0f);
    o1.w = fmaxf(fmaf(dvn, a[7], b1.w), 0.0f);
    *(float4*)&outp[(size_t)node * F + c8]     = o0;
    *(float4*)&outp[(size_t)node * F + c8 + 4] = o1;
}

static inline int blocks_for(int count, int npb) {
    return (count + npb - 1) / npb;
}

// ---------------- launch ----------------
extern "C" void kernel_launch(void* const* d_in, const int* in_sizes, int n_in,
                              void* d_out, int out_size) {
    const float* x  = (const float*)d_in[0];
    const void*  ei = d_in[1];
    const float* W1 = (const float*)d_in[2];
    const float* b1 = (const float*)d_in[3];
    const float* W2 = (const float*)d_in[4];
    const float* b2 = (const float*)d_in[5];
    const float* W3 = (const float*)d_in[6];
    const float* b3 = (const float*)d_in[7];
    const float* W4 = (const float*)d_in[8];
    const float* b4 = (const float*)d_in[9];
    const float* W5 = (const float*)d_in[10];
    const float* b5 = (const float*)d_in[11];
    float* out = (float*)d_out;

    constexpr int SM1 = 3 * 128 * STR * 2;           // 104448
    constexpr int SM2 = (128 + 2 * 64) * 136 * 2;    //  69632
    constexpr int SM3 = (128 + 2 * 32) * 72 * 2;     //  27648

    static float* act = nullptr;
    static __half *ahA, *ahB, *hsA, *hsB;
    static cudaStream_t s1 = nullptr;
    static cudaEvent_t evF, evCsr, evFill1, evG1F, evA1h1, evG2, evA2h1, evG3, evA3h1;
    if (!act) {
        cudaGetSymbolAddress((void**)&act, g_act);
        cudaGetSymbolAddress((void**)&ahA, g_ahA);
        cudaGetSymbolAddress((void**)&ahB, g_ahB);
        cudaGetSymbolAddress((void**)&hsA, g_hsA);
        cudaGetSymbolAddress((void**)&hsB, g_hsB);
        cudaStreamCreateWithFlags(&s1, cudaStreamNonBlocking);
        cudaEventCreateWithFlags(&evF,     cudaEventDisableTiming);
        cudaEventCreateWithFlags(&evCsr,   cudaEventDisableTiming);
        cudaEventCreateWithFlags(&evFill1, cudaEventDisableTiming);
        cudaEventCreateWithFlags(&evG1F,   cudaEventDisableTiming);
        cudaEventCreateWithFlags(&evA1h1,  cudaEventDisableTiming);
        cudaEventCreateWithFlags(&evG2,    cudaEventDisableTiming);
        cudaEventCreateWithFlags(&evA2h1,  cudaEventDisableTiming);
        cudaEventCreateWithFlags(&evG3,    cudaEventDisableTiming);
        cudaEventCreateWithFlags(&evA3h1,  cudaEventDisableTiming);
        cudaFuncSetAttribute(gemm_mma1, cudaFuncAttributeMaxDynamicSharedMemorySize, SM1);
        cudaFuncSetAttribute(gemm_mmaT<128, 64>, cudaFuncAttributeMaxDynamicSharedMemorySize, SM2);
        cudaFuncSetAttribute(gemm_mmaT<64, 32>, cudaFuncAttributeMaxDynamicSharedMemorySize, SM3);
    }

    const int H0 = NSPLIT, H1 = NN - NSPLIT;
    int nb = (NN + 255) / 256;
    int eb = (NE + 255) / 256;
    const int EHALF = NE / 2;

    // fork: CSR build on s1; W split + layer-1 GEMM on s0
    cudaEventRecord(evF, 0);
    cudaStreamWaitEvent(s1, evF, 0);

    k_sniff_zero   <<<nb, 256, 0, s1>>>((const unsigned int*)ei);
    k_deg          <<<eb, 256, 0, s1>>>(ei);
    k_finalize_csr <<<nb, 256, 0, s1>>>();
    cudaEventRecord(evCsr, s1);
    k_fill         <<<(EHALF + 255) / 256, 256, 0, s1>>>(ei, 0, EHALF);
    cudaEventRecord(evFill1, s1);

    k_wsplit1 <<<64, 256>>>(W1);
    k_wsplit2 <<<32, 256>>>(W2);
    k_wsplit3 <<<8, 256>>>(W3);
    gemm_mma1 <<<(NN + 127) / 128, 256, SM1>>>(x);
    cudaStreamWaitEvent(0, evCsr, 0);
    k_fill <<<(NE - EHALF + 255) / 256, 256>>>(ei, EHALF, NE);
    cudaEventRecord(evG1F, 0);   // gemm1 + fill h2 done (s0)

    // ---- layer 1 aggregate, split halves ----
    cudaStreamWaitEvent(s1, evG1F, 0);   // s1 has fill h1 in program order
    aggregate1 <<<blocks_for(H1, 16), 256, 0, s1>>>(b1, NSPLIT);
    cudaEventRecord(evA1h1, s1);

    cudaStreamWaitEvent(0, evFill1, 0);  // s0 needs fill h1 done
    aggregate1 <<<blocks_for(H0, 16), 256>>>(b1, 0);

    // ---- layer 2 gemm (mma), pipelined with A1 half1 ----
    gemm_mmaT<128, 64> <<<H0 / 128, 256, SM2>>>(ahA, hsB, 0);
    cudaStreamWaitEvent(0, evA1h1, 0);
    gemm_mmaT<128, 64> <<<blocks_for(H1, 128), 256, SM2>>>(ahA, hsB, NSPLIT);
    cudaEventRecord(evG2, 0);

    // ---- layer 2 aggregate (fp16 act out), halves ----
    cudaStreamWaitEvent(s1, evG2, 0);
    agg_split64 <<<blocks_for(H1, 32), 256, 0, s1>>>(b2, NSPLIT);
    cudaEventRecord(evA2h1, s1);
    agg_split64 <<<blocks_for(H0, 32), 256>>>(b2, 0);

    // ---- layer 3 gemm (mma), pipelined ----
    gemm_mmaT<64, 32> <<<H0 / 128, 256, SM3>>>(ahB, hsA, 0);
    cudaStreamWaitEvent(0, evA2h1, 0);
    gemm_mmaT<64, 32> <<<blocks_for(H1, 128), 256, SM3>>>(ahB, hsA, NSPLIT);
    cudaEventRecord(evG3, 0);

    // ---- layer 3 aggregate (fp32 act out), halves ----
    cudaStreamWaitEvent(s1, evG3, 0);
    aggregate2<32> <<<blocks_for(H1, 64), 256, 0, s1>>>(b3, act, hsA, NSPLIT);
    cudaEventRecord(evA3h1, s1);
    aggregate2<32> <<<blocks_for(H0, 64), 256>>>(b3, act, hsA, 0);

    // ---- layer 4 gemm (FFMA), pipelined ----
    gemm_small<32, 16> <<<H0 / 256, 256>>>(act, W4, hsB, 0);
    cudaStreamWaitEvent(0, evA3h1, 0);
    gemm_small<32, 16> <<<blocks_for(H1, 256), 256>>>(act, W4, hsB, NSPLIT);

    // ---- tail, sequential on s0 ----
    aggregate2<16> <<<blocks_for(NN, 128), 256>>>(b4, act, hsB, 0);
    gemm_small<16, 8> <<<nb, 256>>>(act, W5, hsA, 0);
    aggregate2<8> <<<blocks_for(NN, 256), 256>>>(b5, out, hsA, 0);
}

// round 16
// speedup vs baseline: 1.0618x; 1.0618x over previous
#include <cuda_runtime.h>
#include <cuda_fp16.h>
#include <cstdint>

#define NN 100000
#define NE 1600000
#define SCAN_B 256
#define NBLK ((NN + SCAN_B - 1) / SCAN_B)   // 391
#define NSPLIT 50176                         // = 392*128 = 196*256

// ---- static device scratch (no allocation allowed) ----
__device__ __align__(16) float  g_dinv[NN];
__device__ __align__(16) int    g_col[NE];
__device__ __align__(16) int    g_rowptr[NN + 1];
__device__ __align__(16) int    g_deg[NN];
__device__ __align__(16) int    g_scan[NN];
__device__ __align__(16) int    g_cursor[NN];
__device__ __align__(16) int    g_bsum[NBLK];
__device__ __align__(16) int    g_boff[NBLK];
// ping-pong hs buffers (odd layers -> A, even layers -> B)
__device__ __align__(16) __half g_hsA[12800000];   // layers 1(128),3(32),5(8)
__device__ __align__(16) __half g_hsB[6400000];    // layers 2(64),4(16)
// fp16 activations
__device__ __align__(16) __half g_ahA[12800000];   // L1 act (128)
__device__ __align__(16) __half g_ahB[6400000];    // L2 act (64)
__device__ __align__(16) float  g_act[3200000];    // L3 (32) / L4 (16) act fp32
// W splits (transposed [n][k])
__device__ __align__(16) __half g_w1h[16384], g_w1l[16384];
__device__ __align__(16) __half g_w2h[8192],  g_w2l[8192];
__device__ __align__(16) __half g_w3h[2048],  g_w3l[2048];
__device__ int g_is64;

// ---------------- small helpers ----------------
__device__ __forceinline__ uint32_t smem_u32(const void* p) {
    uint32_t a;
    asm("{ .reg .u64 t; cvta.to.shared.u64 t, %1; cvt.u32.u64 %0, t; }"
        : "=r"(a) : "l"(p));
    return a;
}
__device__ __forceinline__ void ldsm4(uint32_t* r, uint32_t addr) {
    asm volatile("ldmatrix.sync.aligned.m8n8.x4.shared.b16 {%0,%1,%2,%3}, [%4];"
        : "=r"(r[0]), "=r"(r[1]), "=r"(r[2]), "=r"(r[3]) : "r"(addr));
}
__device__ __forceinline__ void ldsm2(uint32_t* r, uint32_t addr) {
    asm volatile("ldmatrix.sync.aligned.m8n8.x2.shared.b16 {%0,%1}, [%2];"
        : "=r"(r[0]), "=r"(r[1]) : "r"(addr));
}
__device__ __forceinline__ void mma16816(float* c, const uint32_t* a,
                                         const uint32_t* b) {
    asm volatile("mma.sync.aligned.m16n8k16.row.col.f32.f16.f16.f32 "
        "{%0,%1,%2,%3}, {%4,%5,%6,%7}, {%8,%9}, {%0,%1,%2,%3};"
        : "+f"(c[0]), "+f"(c[1]), "+f"(c[2]), "+f"(c[3])
        : "r"(a[0]), "r"(a[1]), "r"(a[2]), "r"(a[3]), "r"(b[0]), "r"(b[1]));
}

// ---------------- sniff + zero deg (merged) ----------------
__global__ void k_sniff_zero(const unsigned int* __restrict__ w) {
    int i = blockIdx.x * blockDim.x + threadIdx.x;
    if (i < NN) g_deg[i] = 0;
    if (i == 0) {
        int is64 = 1;
        for (int q = 0; q < 128; q++)
            if (w[2 * q + 1] != 0u) { is64 = 0; break; }
        g_is64 = is64;
    }
}

// degree pass: reads only dst
__global__ void k_deg(const void* __restrict__ ei) {
    int e = blockIdx.x * blockDim.x + threadIdx.x;
    if (e >= NE) return;
    long long d;
    if (g_is64) {
        d = ((const long long*)ei)[NE + e];
    } else {
        d = ((const int*)ei)[NE + e];
    }
    if (d >= 0 && d < NN)
        atomicAdd(&g_deg[(int)d], 1);
}

__global__ void k_scan1() {
    __shared__ int sm[SCAN_B];
    int tid = threadIdx.x;
    int i = blockIdx.x * SCAN_B + tid;
    sm[tid] = (i < NN) ? g_deg[i] : 0;
    __syncthreads();
#pragma unroll
    for (int off = 1; off < SCAN_B; off <<= 1) {
        int t = (tid >= off) ? sm[tid - off] : 0;
        __syncthreads();
        if (tid >= off) sm[tid] += t;
        __syncthreads();
    }
    if (i < NN) g_scan[i] = sm[tid];
    if (tid == SCAN_B - 1) g_bsum[blockIdx.x] = sm[SCAN_B - 1];
}

__global__ void k_scan2() {
    __shared__ int sm[512];
    int tid = threadIdx.x;
    sm[tid] = (tid < NBLK) ? g_bsum[tid] : 0;
    __syncthreads();
#pragma unroll
    for (int off = 1; off < 512; off <<= 1) {
        int t = (tid >= off) ? sm[tid - off] : 0;
        __syncthreads();
        if (tid >= off) sm[tid] += t;
        __syncthreads();
    }
    if (tid < NBLK) g_boff[tid] = sm[tid] - g_bsum[tid];   // exclusive
}

__global__ void k_finalize_csr() {
    int i = blockIdx.x * blockDim.x + threadIdx.x;
    if (i >= NN) return;
    int incl = g_scan[i] + g_boff[i / SCAN_B];
    int deg = g_deg[i];
    g_rowptr[i] = incl - deg;
    g_cursor[i] = 0;
    g_dinv[i] = rsqrtf((float)deg + 1.0f);
    if (i == NN - 1) g_rowptr[NN] = incl;
}

// fill keyed on dst only (consistent with k_deg); src clamped for safety
__global__ void k_fill(const void* __restrict__ ei, int e0, int e1) {
    int e = e0 + blockIdx.x * blockDim.x + threadIdx.x;
    if (e >= e1) return;
    long long s, d;
    if (g_is64) {
        const long long* p = (const long long*)ei;
        s = p[e]; d = p[NE + e];
    } else {
        const int* p = (const int*)ei;
        s = p[e]; d = p[NE + e];
    }
    if (d >= 0 && d < NN) {
        int sc = (int)s;
        sc = sc < 0 ? 0 : (sc >= NN ? NN - 1 : sc);
        int pos = g_rowptr[(int)d] + atomicAdd(&g_cursor[(int)d], 1);
        g_col[pos] = sc;
    }
}

// ---------------- W transpose + fp16 split ----------------
__global__ void k_wsplit1(const float* __restrict__ W) {
    int idx = blockIdx.x * blockDim.x + threadIdx.x;
    if (idx >= 128 * 128) return;
    int n = idx >> 7, k = idx & 127;
    float v = W[k * 128 + n];
    __half h = __float2half_rn(v);
    g_w1h[idx] = h;
    g_w1l[idx] = __float2half_rn(v - __half2float(h));
}
__global__ void k_wsplit2(const float* __restrict__ W) {
    int idx = blockIdx.x * blockDim.x + threadIdx.x;
    if (idx >= 64 * 128) return;
    int n = idx >> 7, k = idx & 127;
    float v = W[k * 64 + n];
    __half h = __float2half_rn(v);
    g_w2h[idx] = h;
    g_w2l[idx] = __float2half_rn(v - __half2float(h));
}
__global__ void k_wsplit3(const float* __restrict__ W) {
    int idx = blockIdx.x * blockDim.x + threadIdx.x;
    if (idx >= 32 * 64) return;
    int n = idx >> 6, k = idx & 63;
    float v = W[k * 32 + n];
    __half h = __float2half_rn(v);
    g_w3h[idx] = h;
    g_w3l[idx] = __float2half_rn(v - __half2float(h));
}

// =============== layer-1 GEMM: A fp16, W split, fp32 acc ===================
// CTA: 128 rows x 128 cols, K=128, 8 warps (4m x 2n). Writes RAW h -> g_hsA.
#define STR 136
__global__ __launch_bounds__(256) void gemm_mma1(const float* __restrict__ in) {
    extern __shared__ __align__(16) __half sm[];
    __half* ah = sm;
    __half* bh = ah + 128 * STR;
    __half* bl = bh + 128 * STR;
    int tid = threadIdx.x;
    int rowBase = blockIdx.x * 128;

#pragma unroll
    for (int i = 0; i < 16; i++) {
        int idx = tid + i * 256;
        int r = idx >> 5;
        int c4 = (idx & 31) * 4;
        int gr = rowBase + r;
        float4 v = (gr < NN) ? *(const float4*)&in[(size_t)gr * 128 + c4]
                             : make_float4(0.f, 0.f, 0.f, 0.f);
        __half2 hp0 = __floats2half2_rn(v.x, v.y);
        __half2 hp1 = __floats2half2_rn(v.z, v.w);
        int off = r * STR + c4;
        *(__half2*)&ah[off] = hp0;
        *(__half2*)&ah[off + 2] = hp1;
    }
#pragma unroll
    for (int i = 0; i < 8; i++) {
        int idx = tid + i * 256;
        int r = idx >> 4, g = idx & 15;
        int off = r * STR + g * 8;
        *(uint4*)&bh[off] = *(const uint4*)&g_w1h[r * 128 + g * 8];
        *(uint4*)&bl[off] = *(const uint4*)&g_w1l[r * 128 + g * 8];
    }
    __syncthreads();

    int wid = tid >> 5, lane = tid & 31;
    int wm = wid & 3, wn = wid >> 2;
    uint32_t ahb = smem_u32(ah);
    uint32_t bhb = smem_u32(bh), blb = smem_u32(bl);
    int arow = wm * 32 + (lane & 15);
    int acol = (lane >> 4) * 8;
    int brow = wn * 64 + (lane & 7);
    int bcol = ((lane >> 3) & 1) * 8;

    float acc[2][8][4];
#pragma unroll
    for (int m = 0; m < 2; m++)
#pragma unroll
        for (int n = 0; n < 8; n++)
#pragma unroll
            for (int q = 0; q < 4; q++) acc[m][n][q] = 0.0f;

#pragma unroll
    for (int kk = 0; kk < 8; kk++) {
        uint32_t afh[2][4];
#pragma unroll
        for (int m = 0; m < 2; m++) {
            uint32_t ao = (uint32_t)(((arow + m * 16) * STR + kk * 16 + acol) * 2);
            ldsm4(afh[m], ahb + ao);
        }
        uint32_t bfh[8][2], bfl[8][2];
#pragma unroll
        for (int n = 0; n < 8; n++) {
            uint32_t bo = (uint32_t)(((brow + n * 8) * STR + kk * 16 + bcol) * 2);
            ldsm2(bfh[n], bhb + bo);
            ldsm2(bfl[n], blb + bo);
        }
#pragma unroll
        for (int m = 0; m < 2; m++)
#pragma unroll
            for (int n = 0; n < 8; n++) {
                mma16816(acc[m][n], afh[m], bfh[n]);
                mma16816(acc[m][n], afh[m], bfl[n]);
            }
    }

    int r0 = rowBase + wm * 32 + (lane >> 2);
    int cbase = wn * 64 + 2 * (lane & 3);
#pragma unroll
    for (int m = 0; m < 2; m++) {
        int ra = r0 + m * 16, rb = ra + 8;
#pragma unroll
        for (int n = 0; n < 8; n++) {
            int col = cbase + n * 8;
            if (ra < NN) {
                __half2 p = __floats2half2_rn(acc[m][n][0], acc[m][n][1]);
                *(uint32_t*)&g_hsA[(size_t)ra * 128 + col] = *(uint32_t*)&p;
            }
            if (rb < NN) {
                __half2 p = __floats2half2_rn(acc[m][n][2], acc[m][n][3]);
                *(uint32_t*)&g_hsA[(size_t)rb * 128 + col] = *(uint32_t*)&p;
            }
        }
    }
}

// =============== generic mma GEMM: [128 rows, FIN] x [FIN, FOUT] ===========
// A single fp16, W split. Writes hs = dinv*h.
template <int FIN, int FOUT>
__global__ __launch_bounds__(256) void gemm_mmaT(const __half* __restrict__ Ah,
                                                 __half* __restrict__ hsd,
                                                 int rowBase0) {
    constexpr int AST = FIN + 8;
    constexpr int GPR = FIN / 8;
    constexpr int NT = FOUT / 16;
    extern __shared__ __align__(16) __half sm[];
    __half* ah = sm;
    __half* bh = ah + 128 * AST;
    __half* bl = bh + FOUT * AST;
    int tid = threadIdx.x;
    int rowBase = rowBase0 + blockIdx.x * 128;

    const __half* Bh = (FIN == 128) ? g_w2h : g_w3h;
    const __half* Bl = (FIN == 128) ? g_w2l : g_w3l;

#pragma unroll
    for (int i = 0; i < FIN / 16; i++) {
        int idx = tid + i * 256;
        int r = idx / GPR, g = idx % GPR;
        int gr = rowBase + r;
        int off = r * AST + g * 8;
        if (gr < NN) {
            *(uint4*)&ah[off] = *(const uint4*)&Ah[(size_t)gr * FIN + g * 8];
        } else {
            *(uint4*)&ah[off] = make_uint4(0, 0, 0, 0);
        }
    }
#pragma unroll
    for (int i = 0; i < (FOUT * GPR + 255) / 256; i++) {
        int idx = tid + i * 256;
        if (idx < FOUT * GPR) {
            int r = idx / GPR, g = idx % GPR;
            int off = r * AST + g * 8;
            *(uint4*)&bh[off] = *(const uint4*)&Bh[r * FIN + g * 8];
            *(uint4*)&bl[off] = *(const uint4*)&Bl[r * FIN + g * 8];
        }
    }
    __syncthreads();

    int wid = tid >> 5, lane = tid & 31;
    int wm = wid & 3, wn = wid >> 2;
    uint32_t ahb = smem_u32(ah);
    uint32_t bhb = smem_u32(bh), blb = smem_u32(bl);
    int arow = wm * 32 + (lane & 15);
    int acol = (lane >> 4) * 8;
    int brow = wn * (FOUT / 2) + (lane & 7);
    int bcol = ((lane >> 3) & 1) * 8;

    float acc[2][NT][4];
#pragma unroll
    for (int m = 0; m < 2; m++)
#pragma unroll
        for (int n = 0; n < NT; n++)
#pragma unroll
            for (int q = 0; q < 4; q++) acc[m][n][q] = 0.0f;

#pragma unroll
    for (int kk = 0; kk < FIN / 16; kk++) {
        uint32_t afh[2][4];
#pragma unroll
        for (int m = 0; m < 2; m++) {
            uint32_t ao = (uint32_t)(((arow + m * 16) * AST + kk * 16 + acol) * 2);
            ldsm4(afh[m], ahb + ao);
        }
        uint32_t bfh[NT][2], bfl[NT][2];
#pragma unroll
        for (int n = 0; n < NT; n++) {
            uint32_t bo = (uint32_t)(((brow + n * 8) * AST + kk * 16 + bcol) * 2);
            ldsm2(bfh[n], bhb + bo);
            ldsm2(bfl[n], blb + bo);
        }
#pragma unroll
        for (int m = 0; m < 2; m++)
#pragma unroll
            for (int n = 0; n < NT; n++) {
                mma16816(acc[m][n], afh[m], bfh[n]);
                mma16816(acc[m][n], afh[m], bfl[n]);
            }
    }

    int r0 = rowBase + wm * 32 + (lane >> 2);
    int cbase = wn * (FOUT / 2) + 2 * (lane & 3);
#pragma unroll
    for (int m = 0; m < 2; m++) {
        int ra = r0 + m * 16, rb = ra + 8;
        float da = (ra < NN) ? g_dinv[ra] : 0.0f;
        float db = (rb < NN) ? g_dinv[rb] : 0.0f;
#pragma unroll
        for (int n = 0; n < NT; n++) {
            int col = cbase + n * 8;
            if (ra < NN) {
                __half2 p = __floats2half2_rn(acc[m][n][0] * da, acc[m][n][1] * da);
                *(uint32_t*)&hsd[(size_t)ra * FOUT + col] = *(uint32_t*)&p;
            }
            if (rb < NN) {
                __half2 p = __floats2half2_rn(acc[m][n][2] * db, acc[m][n][3] * db);
                *(uint32_t*)&hsd[(size_t)rb * FOUT + col] = *(uint32_t*)&p;
            }
        }
    }
}

// ---------------- GEMM, layers 4-5 (FFMA) ----------------
template <int FIN, int FOUT>
__global__ __launch_bounds__(256) void gemm_small(const float* __restrict__ in,
                                                  const float* __restrict__ W,
                                                  __half* __restrict__ hsd,
                                                  int rowBase0) {
    __shared__ float ws[FIN * FOUT];
    __shared__ float xs[256][9];
    int tid = threadIdx.x;
    for (int i = tid; i < FIN * FOUT; i += 256) ws[i] = W[i];

    int rowBase = rowBase0 + blockIdx.x * 256;
    int row = rowBase + tid;
    float acc[FOUT];
#pragma unroll
    for (int j = 0; j < FOUT; j++) acc[j] = 0.0f;

    for (int k0 = 0; k0 < FIN; k0 += 8) {
#pragma unroll
        for (int i = 0; i < 8; i++) {
            int idx = tid + i * 256;
            int r = idx >> 3, c = idx & 7;
            int gr = rowBase + r;
            xs[r][c] = (gr < NN) ? in[(size_t)gr * FIN + k0 + c] : 0.0f;
        }
        __syncthreads();
#pragma unroll
        for (int k = 0; k < 8; k++) {
            float xv = xs[tid][k];
            const float* wrow = &ws[(k0 + k) * FOUT];
#pragma unroll
            for (int j = 0; j < FOUT; j++)
                acc[j] = fmaf(xv, wrow[j], acc[j]);
        }
        __syncthreads();
    }

    if (row < NN) {
        float dv = g_dinv[row];
#pragma unroll
        for (int j = 0; j < FOUT; j += 8) {
            __half2 ph[4];
#pragma unroll
            for (int q = 0; q < 4; q++)
                ph[q] = __floats2half2_rn(acc[j + 2 * q] * dv,
                                          acc[j + 2 * q + 1] * dv);
            *(uint4*)&hsd[(size_t)row * FOUT + j] = *(uint4*)ph;
        }
    }
}

// ---- aggregate layer 1: raw fp16 h (g_hsA), per-edge dinv; fp16 act ----
__global__ __launch_bounds__(256) void aggregate1(const float* __restrict__ bias,
                                                  int base) {
    constexpr int F = 128;
    int warp = (blockIdx.x * 256 + threadIdx.x) >> 5;
    int lane = threadIdx.x & 31;
    int node = base + warp * 2 + (lane >> 4);
    int c8 = (lane & 15) * 8;
    if (node >= NN) return;

    float dvn = g_dinv[node];
    int beg = g_rowptr[node];
    int end = g_rowptr[node + 1];

    float a[8];
    {
        uint4 raw = *(const uint4*)&g_hsA[(size_t)node * F + c8];
        const __half2* hp = (const __half2*)&raw;
#pragma unroll
        for (int q = 0; q < 4; q++) {
            float2 f = __half22float2(hp[q]);
            a[2 * q]     = dvn * f.x;
            a[2 * q + 1] = dvn * f.y;
        }
    }

    int e = beg;
    for (; e + 1 < end; e += 2) {
        int s0 = g_col[e];
        int s1 = g_col[e + 1];
        float d0 = g_dinv[s0];
        float d1 = g_dinv[s1];
        uint4 r0 = *(const uint4*)&g_hsA[(size_t)s0 * F + c8];
        uint4 r1 = *(const uint4*)&g_hsA[(size_t)s1 * F + c8];
        const __half2* h0 = (const __half2*)&r0;
        const __half2* h1 = (const __half2*)&r1;
#pragma unroll
        for (int q = 0; q < 4; q++) {
            float2 f0 = __half22float2(h0[q]);
            float2 f1 = __half22float2(h1[q]);
            a[2 * q]     = fmaf(d0, f0.x, fmaf(d1, f1.x, a[2 * q]));
            a[2 * q + 1] = fmaf(d0, f0.y, fmaf(d1, f1.y, a[2 * q + 1]));
        }
    }
    if (e < end) {
        int s = g_col[e];
        float ds = g_dinv[s];
        uint4 r = *(const uint4*)&g_hsA[(size_t)s * F + c8];
        const __half2* h = (const __half2*)&r;
#pragma unroll
        for (int q = 0; q < 4; q++) {
            float2 f = __half22float2(h[q]);
            a[2 * q]     = fmaf(ds, f.x, a[2 * q]);
            a[2 * q + 1] = fmaf(ds, f.y, a[2 * q + 1]);
        }
    }

    __half hh[8];
#pragma unroll
    for (int q = 0; q < 8; q++) {
        float b = bias[c8 + q];
        hh[q] = __float2half_rn(fmaxf(fmaf(dvn, a[q], b), 0.0f));
    }
    *(uint4*)&g_ahA[(size_t)node * F + c8] = *(uint4*)hh;
}

// ---- aggregate layer 2 (F=64, hs in g_hsB pre-scaled): fp16 act out ----
__global__ __launch_bounds__(256) void agg_split64(const float* __restrict__ bias,
                                                   int base) {
    constexpr int F = 64;
    int warp = (blockIdx.x * 256 + threadIdx.x) >> 5;
    int lane = threadIdx.x & 31;
    int node = base + warp * 4 + lane / 8;
    int c8 = (lane % 8) * 8;
    if (node >= NN) return;

    float dvn = g_dinv[node];
    int beg = g_rowptr[node];
    int end = g_rowptr[node + 1];

    float a[8];
    {
        uint4 raw = *(const uint4*)&g_hsB[(size_t)node * F + c8];
        const __half2* hp = (const __half2*)&raw;
#pragma unroll
        for (int q = 0; q < 4; q++) {
            float2 f = __half22float2(hp[q]);
            a[2 * q] = f.x;
            a[2 * q + 1] = f.y;
        }
    }
    int e = beg;
    for (; e + 1 < end; e += 2) {
        int s0 = g_col[e];
        int s1 = g_col[e + 1];
        uint4 r0 = *(const uint4*)&g_hsB[(size_t)s0 * F + c8];
        uint4 r1 = *(const uint4*)&g_hsB[(size_t)s1 * F + c8];
        const __half2* h0 = (const __half2*)&r0;
        const __half2* h1 = (const __half2*)&r1;
#pragma unroll
        for (int q = 0; q < 4; q++) {
            float2 f0 = __half22float2(h0[q]);
            float2 f1 = __half22float2(h1[q]);
            a[2 * q]     += f0.x + f1.x;
            a[2 * q + 1] += f0.y + f1.y;
        }
    }
    if (e < end) {
        int s = g_col[e];
        uint4 r = *(const uint4*)&g_hsB[(size_t)s * F + c8];
        const __half2* h = (const __half2*)&r;
#pragma unroll
        for (int q = 0; q < 4; q++) {
            float2 f = __half22float2(h[q]);
            a[2 * q]     += f.x;
            a[2 * q + 1] += f.y;
        }
    }

    __half hh[8];
#pragma unroll
    for (int q = 0; q < 8; q++) {
        float b = bias[c8 + q];
        hh[q] = __float2half_rn(fmaxf(fmaf(dvn, a[q], b), 0.0f));
    }
    *(uint4*)&g_ahB[(size_t)node * F + c8] = *(uint4*)hh;
}

// ---- aggregate layers 3-5: hs pre-scaled; fp32 out ----
template <int F>
__global__ __launch_bounds__(256) void aggregate2(const float* __restrict__ bias,
                                                  float* __restrict__ outp,
                                                  const __half* __restrict__ hs,
                                                  int base) {
    constexpr int L = F / 8;
    constexpr int NPW = 32 / L;
    int warp = (blockIdx.x * 256 + threadIdx.x) >> 5;
    int lane = threadIdx.x & 31;
    int node = base + warp * NPW + lane / L;
    int c8 = (lane % L) * 8;
    if (node >= NN) return;

    float dvn = g_dinv[node];
    int beg = g_rowptr[node];
    int end = g_rowptr[node + 1];

    float a[8];
    {
        uint4 raw = *(const uint4*)&hs[(size_t)node * F + c8];
        const __half2* hp = (const __half2*)&raw;
#pragma unroll
        for (int q = 0; q < 4; q++) {
            float2 f = __half22float2(hp[q]);
            a[2 * q] = f.x;
            a[2 * q + 1] = f.y;
        }
    }
    int e = beg;
    for (; e + 1 < end; e += 2) {
        int s0 = g_col[e];
        int s1 = g_col[e + 1];
        uint4 r0 = *(const uint4*)&hs[(size_t)s0 * F + c8];
        uint4 r1 = *(const uint4*)&hs[(size_t)s1 * F + c8];
        const __half2* h0 = (const __half2*)&r0;
        const __half2* h1 = (const __half2*)&r1;
#pragma unroll
        for (int q = 0; q < 4; q++) {
            float2 f0 = __half22float2(h0[q]);
            float2 f1 = __half22float2(h1[q]);
            a[2 * q]     += f0.x + f1.x;
            a[2 * q + 1] += f0.y + f1.y;
        }
    }
    if (e < end) {
        int s = g_col[e];
        uint4 r = *(const uint4*)&hs[(size_t)s * F + c8];
        const __half2* h = (const __half2*)&r;
#pragma unroll
        for (int q = 0; q < 4; q++) {
            float2 f = __half22float2(h[q]);
            a[2 * q]     += f.x;
            a[2 * q + 1] += f.y;
        }
    }

    float4 b0 = *(const float4*)&bias[c8];
    float4 b1 = *(const float4*)&bias[c8 + 4];
    float4 o0, o1;
    o0.x = fmaxf(fmaf(dvn, a[0], b0.x), 0.0f);
    o0.y = fmaxf(fmaf(dvn, a[1], b0.y), 0.0f);
    o0.z = fmaxf(fmaf(dvn, a[2], b0.z), 0.0f);
    o0.w = fmaxf(fmaf(dvn, a[3], b0.w), 0.0f);
    o1.x = fmaxf(fmaf(dvn, a[4], b1.x), 0.0f);
    o1.y = fmaxf(fmaf(dvn, a[5], b1.y), 0.0f);
    o1.z = fmaxf(fmaf(dvn, a[6], b1.z), 0.0f);
    o1.w = fmaxf(fmaf(dvn, a[7], b1.w), 0.0f);
    *(float4*)&outp[(size_t)node * F + c8]     = o0;
    *(float4*)&outp[(size_t)node * F + c8 + 4] = o1;
}

static inline int blocks_for(int count, int npb) {
    return (count + npb - 1) / npb;
}

// ---------------- launch ----------------
extern "C" void kernel_launch(void* const* d_in, const int* in_sizes, int n_in,
                              void* d_out, int out_size) {
    const float* x  = (const float*)d_in[0];
    const void*  ei = d_in[1];
    const float* W1 = (const float*)d_in[2];
    const float* b1 = (const float*)d_in[3];
    const float* W2 = (const float*)d_in[4];
    const float* b2 = (const float*)d_in[5];
    const float* W3 = (const float*)d_in[6];
    const float* b3 = (const float*)d_in[7];
    const float* W4 = (const float*)d_in[8];
    const float* b4 = (const float*)d_in[9];
    const float* W5 = (const float*)d_in[10];
    const float* b5 = (const float*)d_in[11];
    float* out = (float*)d_out;

    constexpr int SM1 = 3 * 128 * STR * 2;           // 104448
    constexpr int SM2 = (128 + 2 * 64) * 136 * 2;    //  69632
    constexpr int SM3 = (128 + 2 * 32) * 72 * 2;     //  27648

    static float* act = nullptr;
    static __half *ahA, *ahB, *hsA, *hsB;
    static cudaStream_t s1 = nullptr;
    static cudaEvent_t evF, evCsr, evFill1, evG1F, evA1h1, evG2, evA2h1, evG3, evA3h1;
    if (!act) {
        cudaGetSymbolAddress((void**)&act, g_act);
        cudaGetSymbolAddress((void**)&ahA, g_ahA);
        cudaGetSymbolAddress((void**)&ahB, g_ahB);
        cudaGetSymbolAddress((void**)&hsA, g_hsA);
        cudaGetSymbolAddress((void**)&hsB, g_hsB);
        cudaStreamCreateWithFlags(&s1, cudaStreamNonBlocking);
        cudaEventCreateWithFlags(&evF,     cudaEventDisableTiming);
        cudaEventCreateWithFlags(&evCsr,   cudaEventDisableTiming);
        cudaEventCreateWithFlags(&evFill1, cudaEventDisableTiming);
        cudaEventCreateWithFlags(&evG1F,   cudaEventDisableTiming);
        cudaEventCreateWithFlags(&evA1h1,  cudaEventDisableTiming);
        cudaEventCreateWithFlags(&evG2,    cudaEventDisableTiming);
        cudaEventCreateWithFlags(&evA2h1,  cudaEventDisableTiming);
        cudaEventCreateWithFlags(&evG3,    cudaEventDisableTiming);
        cudaEventCreateWithFlags(&evA3h1,  cudaEventDisableTiming);
        cudaFuncSetAttribute(gemm_mma1, cudaFuncAttributeMaxDynamicSharedMemorySize, SM1);
        cudaFuncSetAttribute(gemm_mmaT<128, 64>, cudaFuncAttributeMaxDynamicSharedMemorySize, SM2);
        cudaFuncSetAttribute(gemm_mmaT<64, 32>, cudaFuncAttributeMaxDynamicSharedMemorySize, SM3);
    }

    const int H0 = NSPLIT, H1 = NN - NSPLIT;
    int nb = (NN + 255) / 256;
    int eb = (NE + 255) / 256;
    const int EHALF = NE / 2;

    // fork: CSR build on s1; W split + layer-1 GEMM on s0
    cudaEventRecord(evF, 0);
    cudaStreamWaitEvent(s1, evF, 0);

    k_sniff_zero   <<<nb, 256, 0, s1>>>((const unsigned int*)ei);
    k_deg          <<<eb, 256, 0, s1>>>(ei);
    k_scan1        <<<NBLK, SCAN_B, 0, s1>>>();
    k_scan2        <<<1, 512, 0, s1>>>();
    k_finalize_csr <<<nb, 256, 0, s1>>>();
    cudaEventRecord(evCsr, s1);
    k_fill         <<<(EHALF + 255) / 256, 256, 0, s1>>>(ei, 0, EHALF);
    cudaEventRecord(evFill1, s1);

    k_wsplit1 <<<64, 256>>>(W1);
    gemm_mma1 <<<(NN + 127) / 128, 256, SM1>>>(x);
    k_wsplit2 <<<32, 256>>>(W2);
    k_wsplit3 <<<8, 256>>>(W3);
    cudaStreamWaitEvent(0, evCsr, 0);
    k_fill <<<(NE - EHALF + 255) / 256, 256>>>(ei, EHALF, NE);
    cudaEventRecord(evG1F, 0);   // gemm1 + fill h2 done (s0)

    // ---- layer 1 aggregate, split halves ----
    cudaStreamWaitEvent(s1, evG1F, 0);   // s1 has fill h1 in program order
    aggregate1 <<<blocks_for(H1, 16), 256, 0, s1>>>(b1, NSPLIT);
    cudaEventRecord(evA1h1, s1);

    cudaStreamWaitEvent(0, evFill1, 0);  // s0 needs fill h1 done
    aggregate1 <<<blocks_for(H0, 16), 256>>>(b1, 0);

    // ---- layer 2 gemm (mma), pipelined with A1 half1 ----
    gemm_mmaT<128, 64> <<<H0 / 128, 256, SM2>>>(ahA, hsB, 0);
    cudaStreamWaitEvent(0, evA1h1, 0);
    gemm_mmaT<128, 64> <<<blocks_for(H1, 128), 256, SM2>>>(ahA, hsB, NSPLIT);
    cudaEventRecord(evG2, 0);

    // ---- layer 2 aggregate (fp16 act out), halves ----
    cudaStreamWaitEvent(s1, evG2, 0);
    agg_split64 <<<blocks_for(H1, 32), 256, 0, s1>>>(b2, NSPLIT);
    cudaEventRecord(evA2h1, s1);
    agg_split64 <<<blocks_for(H0, 32), 256>>>(b2, 0);

    // ---- layer 3 gemm (mma), pipelined ----
    gemm_mmaT<64, 32> <<<H0 / 128, 256, SM3>>>(ahB, hsA, 0);
    cudaStreamWaitEvent(0, evA2h1, 0);
    gemm_mmaT<64, 32> <<<blocks_for(H1, 128), 256, SM3>>>(ahB, hsA, NSPLIT);
    cudaEventRecord(evG3, 0);

    // ---- layer 3 aggregate (fp32 act out), halves ----
    cudaStreamWaitEvent(s1, evG3, 0);
    aggregate2<32> <<<blocks_for(H1, 64), 256, 0, s1>>>(b3, act, hsA, NSPLIT);
    cudaEventRecord(evA3h1, s1);
    aggregate2<32> <<<blocks_for(H0, 64), 256>>>(b3, act, hsA, 0);

    // ---- layer 4 gemm (FFMA), pipelined ----
    gemm_small<32, 16> <<<H0 / 256, 256>>>(act, W4, hsB, 0);
    cudaStreamWaitEvent(0, evA3h1, 0);
    gemm_small<32, 16> <<<blocks_for(H1, 256), 256>>>(act, W4, hsB, NSPLIT);

    // ---- tail, sequential on s0 ----
    aggregate2<16> <<<blocks_for(NN, 128), 256>>>(b4, act, hsB, 0);
    gemm_small<16, 8> <<<nb, 256>>>(act, W5, hsA, 0);
    aggregate2<8> <<<blocks_for(NN, 256), 256>>>(b5, out, hsA, 0);
}